// round 7
// baseline (speedup 1.0000x reference)
#include <cuda_runtime.h>
#include <cstdint>

// TaylorExp: x [4,16,4096,16] f32 -> out [4,16,4096,273] f32
// out_row = [1, 0.5*x, vec(x x^T) / (4*sqrt(2))]
//
// R7: 8 rows per warp, 256-bit streaming stores (st.global.cs.v8.b32).
// Group-of-8 output slice = 8736 B (32B-aligned), 273 v8-stores per warp.
// Table-driven decode: every element is PQ[a]*PQ[b]; per-v8 entry = 2 uint4.

#define WARPS_PER_BLOCK 8
#define THREADS (WARPS_PER_BLOCK * 32)

static constexpr int TOTAL_ROWS  = 4 * 16 * 4096;   // 262144
static constexpr int GROUPS8     = TOTAL_ROWS / 8;  // 32768 (8 rows per warp)
static constexpr int V8_PER_GRP  = 273;             // 8*273/8 vectors of 8 floats

__device__ __forceinline__ float lds_f32(unsigned addr) {
    float v;
    asm volatile("ld.shared.f32 %0, [%1];" : "=f"(v) : "r"(addr));
    return v;
}

__global__ __launch_bounds__(THREADS)
void TaylorExp_14783277432863_kernel(const float* __restrict__ x,
                                     float* __restrict__ out) {
    __shared__ uint4 tab[273 * 2];                  // 8736 B, block-shared
    __shared__ float pq[WARPS_PER_BLOCK][272];      // P[136] | Q[136] per warp

    const int tid  = threadIdx.x;
    const int warp = tid >> 5;
    const int lane = tid & 31;
    const int group = blockIdx.x * WARPS_PER_BLOCK + warp;   // grid exact

    // ---- build offset table (identical for all groups): 8 elems per entry ----
    for (int k = tid; k < 273; k += THREADS) {
        unsigned w[8];
        #pragma unroll
        for (int c = 0; c < 8; ++c) {
            const int ec  = 8 * k + c;          // 0..2183
            const int row = ec / 273;           // 0..7 (setup-only division)
            const int f   = ec - row * 273;
            int ia, ib;                         // float indices into pq[][272]
            if (f == 0)       { ia = row * 17;          ib = 136 + row * 17; }
            else if (f <= 16) { ia = row * 17 + f;      ib = 136 + row * 17; }
            else {
                const int q = f - 17;
                ia = row * 17 + 1 + (q >> 4);
                ib = 136 + row * 17 + 1 + (q & 15);
            }
            w[c] = (unsigned)(ia * 4) | ((unsigned)(ib * 4) << 16);  // byte offs
        }
        tab[2 * k]     = make_uint4(w[0], w[1], w[2], w[3]);
        tab[2 * k + 1] = make_uint4(w[4], w[5], w[6], w[7]);
    }

    // ---- fill per-warp P/Q (pre-scaled inputs): 8 rows x 16 floats ----
    const float4* xg = reinterpret_cast<const float4*>(x) + (size_t)group * 32;
    {
        float4 v = __ldg(&xg[lane]);            // all 32 lanes, one float4 each
        const int row = lane >> 2, part = lane & 3;
        float* P = pq[warp];
        float* Q = pq[warp] + 136;
        const int bi = row * 17 + 1 + part * 4;
        P[bi + 0] = 0.5f * v.x;  P[bi + 1] = 0.5f * v.y;
        P[bi + 2] = 0.5f * v.z;  P[bi + 3] = 0.5f * v.w;
        const float c2 = 0.5f * 0.70710678118654752f;   // 0.5/sqrt(2)
        Q[bi + 0] = c2 * v.x;    Q[bi + 1] = c2 * v.y;
        Q[bi + 2] = c2 * v.z;    Q[bi + 3] = c2 * v.w;
    }
    if (lane < 8) {                             // unit entries (const/linear)
        pq[warp][lane * 17]       = 1.0f;       // P row heads
        pq[warp][136 + lane * 17] = 1.0f;       // Q row heads
    }
    __syncthreads();

    const unsigned sb = (unsigned)__cvta_generic_to_shared(&pq[warp][0]);
    char* og = reinterpret_cast<char*>(out) + (size_t)group * (273 * 32);

    #pragma unroll
    for (int it = 0; it < 9; ++it) {
        const int k = lane + it * 32;
        if (it < 8 || k < V8_PER_GRP) {         // 273 = 8*32 + 17
            const uint4 t0 = tab[2 * k];
            const uint4 t1 = tab[2 * k + 1];
            unsigned r0 = __float_as_uint(
                lds_f32(sb + (t0.x & 0xFFFFu)) * lds_f32(sb + (t0.x >> 16)));
            unsigned r1 = __float_as_uint(
                lds_f32(sb + (t0.y & 0xFFFFu)) * lds_f32(sb + (t0.y >> 16)));
            unsigned r2 = __float_as_uint(
                lds_f32(sb + (t0.z & 0xFFFFu)) * lds_f32(sb + (t0.z >> 16)));
            unsigned r3 = __float_as_uint(
                lds_f32(sb + (t0.w & 0xFFFFu)) * lds_f32(sb + (t0.w >> 16)));
            unsigned r4 = __float_as_uint(
                lds_f32(sb + (t1.x & 0xFFFFu)) * lds_f32(sb + (t1.x >> 16)));
            unsigned r5 = __float_as_uint(
                lds_f32(sb + (t1.y & 0xFFFFu)) * lds_f32(sb + (t1.y >> 16)));
            unsigned r6 = __float_as_uint(
                lds_f32(sb + (t1.z & 0xFFFFu)) * lds_f32(sb + (t1.z >> 16)));
            unsigned r7 = __float_as_uint(
                lds_f32(sb + (t1.w & 0xFFFFu)) * lds_f32(sb + (t1.w >> 16)));
            asm volatile(
                "st.global.cs.v8.b32 [%0], {%1,%2,%3,%4,%5,%6,%7,%8};"
                :: "l"(og + (size_t)k * 32),
                   "r"(r0), "r"(r1), "r"(r2), "r"(r3),
                   "r"(r4), "r"(r5), "r"(r6), "r"(r7)
                : "memory");
        }
    }
}

extern "C" void kernel_launch(void* const* d_in, const int* in_sizes, int n_in,
                              void* d_out, int out_size) {
    const float* x = (const float*)d_in[0];
    float* out = (float*)d_out;
    (void)in_sizes; (void)n_in; (void)out_size;

    const int blocks = GROUPS8 / WARPS_PER_BLOCK;   // 4096
    TaylorExp_14783277432863_kernel<<<blocks, THREADS>>>(x, out);
}

// round 9
// speedup vs baseline: 1.1614x; 1.1614x over previous
#include <cuda_runtime.h>
#include <cstdint>

// TaylorExp: x [4,16,4096,16] f32 -> out [4,16,4096,273] f32
// out_row = [1, 0.5*x, vec(x x^T) / (4*sqrt(2))]
//
// R8: exact R4 hot path (table decode, STG.128 with st.global.cs evict-first
// streaming stores, 4-row groups, plain __ldg input loads) with 512-thread
// blocks: half the blocks -> half the redundant table-build work.

#define WARPS_PER_BLOCK 16
#define THREADS (WARPS_PER_BLOCK * 32)

static constexpr int TOTAL_ROWS  = 4 * 16 * 4096;   // 262144
static constexpr int GROUPS      = TOTAL_ROWS / 4;  // 65536 (4 rows per warp)
static constexpr int VEC_PER_GRP = 273;             // float4 per group

__device__ __forceinline__ float lds_f32(unsigned addr) {
    float v;
    asm volatile("ld.shared.f32 %0, [%1];" : "=f"(v) : "r"(addr));
    return v;
}

__device__ __forceinline__ void stg_cs_v4(float4* p, float4 v) {
    asm volatile("st.global.cs.v4.f32 [%0], {%1, %2, %3, %4};"
                 :: "l"(p), "f"(v.x), "f"(v.y), "f"(v.z), "f"(v.w)
                 : "memory");
}

__global__ __launch_bounds__(THREADS)
void TaylorExp_14783277432863_kernel(const float* __restrict__ x,
                                     float* __restrict__ out) {
    __shared__ uint4 tab[273];                     // 4368 B, block-shared
    __shared__ float pq[WARPS_PER_BLOCK][136];     // P[68] | Q[68] per warp

    const int tid  = threadIdx.x;
    const int warp = tid >> 5;
    const int lane = tid & 31;
    const int group = blockIdx.x * WARPS_PER_BLOCK + warp;   // grid exact

    // ---- build offset table (identical for all groups) ----
    for (int k = tid; k < 273; k += THREADS) {
        unsigned w[4];
        #pragma unroll
        for (int c = 0; c < 4; ++c) {
            const int ec  = 4 * k + c;
            const int row = (ec >= 273) + (ec >= 546) + (ec >= 819);
            const int f   = ec - row * 273;
            int ia, ib;                 // float indices into pq[warp][136]
            if (f == 0)       { ia = row * 17;          ib = 68 + row * 17; }
            else if (f <= 16) { ia = row * 17 + f;      ib = 68 + row * 17; }
            else {
                const int q = f - 17;
                ia = row * 17 + 1 + (q >> 4);
                ib = 68 + row * 17 + 1 + (q & 15);
            }
            w[c] = (unsigned)(ia * 4) | ((unsigned)(ib * 4) << 16);  // byte offs
        }
        tab[k] = make_uint4(w[0], w[1], w[2], w[3]);
    }

    // ---- fill per-warp P/Q (pre-scaled inputs) ----
    const float4* xg = reinterpret_cast<const float4*>(x) + (size_t)group * 16;
    if (lane < 16) {
        float4 v = __ldg(&xg[lane]);
        const int row = lane >> 2, part = lane & 3;
        float* P = pq[warp];
        float* Q = pq[warp] + 68;
        const int bi = row * 17 + 1 + part * 4;
        P[bi + 0] = 0.5f * v.x;  P[bi + 1] = 0.5f * v.y;
        P[bi + 2] = 0.5f * v.z;  P[bi + 3] = 0.5f * v.w;
        const float c2 = 0.5f * 0.70710678118654752f;
        Q[bi + 0] = c2 * v.x;    Q[bi + 1] = c2 * v.y;
        Q[bi + 2] = c2 * v.z;    Q[bi + 3] = c2 * v.w;
    }
    if (lane < 4) {                          // unit entries for const/linear
        pq[warp][lane * 17]      = 1.0f;
        pq[warp][68 + lane * 17] = 1.0f;
    }
    __syncthreads();

    const unsigned sb = (unsigned)__cvta_generic_to_shared(&pq[warp][0]);
    float4* og = reinterpret_cast<float4*>(out) + (size_t)group * VEC_PER_GRP;

    #pragma unroll
    for (int it = 0; it < 9; ++it) {
        const int k = lane + it * 32;
        if (it < 8 || k < VEC_PER_GRP) {     // 273 = 8*32 + 17
            const uint4 cd = tab[k];
            float4 v;
            v.x = lds_f32(sb + (cd.x & 0xFFFFu)) * lds_f32(sb + (cd.x >> 16));
            v.y = lds_f32(sb + (cd.y & 0xFFFFu)) * lds_f32(sb + (cd.y >> 16));
            v.z = lds_f32(sb + (cd.z & 0xFFFFu)) * lds_f32(sb + (cd.z >> 16));
            v.w = lds_f32(sb + (cd.w & 0xFFFFu)) * lds_f32(sb + (cd.w >> 16));
            stg_cs_v4(og + k, v);            // evict-first streaming store
        }
    }
}

extern "C" void kernel_launch(void* const* d_in, const int* in_sizes, int n_in,
                              void* d_out, int out_size) {
    const float* x = (const float*)d_in[0];
    float* out = (float*)d_out;
    (void)in_sizes; (void)n_in; (void)out_size;

    const int blocks = GROUPS / WARPS_PER_BLOCK;   // 4096
    TaylorExp_14783277432863_kernel<<<blocks, THREADS>>>(x, out);
}

// round 11
// speedup vs baseline: 1.3400x; 1.1538x over previous
#include <cuda_runtime.h>
#include <cstdint>

// TaylorExp: x [4,16,4096,16] f32 -> out [4,16,4096,273] f32
// out_row = [1, 0.5*x, vec(x x^T) / (4*sqrt(2))]
//
// R10: R9 with the constexpr-init fix. Exact R4 hot path (8 warps/256 thr,
// table-driven decode, STG.128 st.global.cs evict-first streaming stores);
// the 273-entry offset table is built at compile time and merely copied
// from a __device__ global into shared (straight-line LDG+STS, no branches).

#define WARPS_PER_BLOCK 8
#define THREADS (WARPS_PER_BLOCK * 32)

static constexpr int TOTAL_ROWS  = 4 * 16 * 4096;   // 262144
static constexpr int GROUPS      = TOTAL_ROWS / 4;  // 65536 (4 rows per warp)
static constexpr int VEC_PER_GRP = 273;             // float4 per group

// ---- compile-time offset table ----------------------------------------
// Entry word for output element ec (0..1091): two byte offsets into the
// per-warp pq[136] array (P[68] | Q[68]), packed 16b|16b.
struct TabInit {
    unsigned w[VEC_PER_GRP * 4];
    constexpr TabInit() : w() {
        for (int ec = 0; ec < VEC_PER_GRP * 4; ++ec) {
            const int row = ec / 273;
            const int f   = ec - row * 273;
            int ia = 0, ib = 0;
            if (f == 0)       { ia = row * 17;          ib = 68 + row * 17; }
            else if (f <= 16) { ia = row * 17 + f;      ib = 68 + row * 17; }
            else {
                const int q = f - 17;
                ia = row * 17 + 1 + (q >> 4);
                ib = 68 + row * 17 + 1 + (q & 15);
            }
            w[ec] = (unsigned)(ia * 4) | ((unsigned)(ib * 4) << 16);
        }
    }
};
__device__ const TabInit g_tab = TabInit();

__device__ __forceinline__ float lds_f32(unsigned addr) {
    float v;
    asm volatile("ld.shared.f32 %0, [%1];" : "=f"(v) : "r"(addr));
    return v;
}

__device__ __forceinline__ void stg_cs_v4(float4* p, float4 v) {
    asm volatile("st.global.cs.v4.f32 [%0], {%1, %2, %3, %4};"
                 :: "l"(p), "f"(v.x), "f"(v.y), "f"(v.z), "f"(v.w)
                 : "memory");
}

__global__ __launch_bounds__(THREADS)
void TaylorExp_14783277432863_kernel(const float* __restrict__ x,
                                     float* __restrict__ out) {
    __shared__ uint4 tab[VEC_PER_GRP];             // 4368 B, block-shared
    __shared__ float pq[WARPS_PER_BLOCK][136];     // P[68] | Q[68] per warp

    const int tid  = threadIdx.x;
    const int warp = tid >> 5;
    const int lane = tid & 31;
    const int group = blockIdx.x * WARPS_PER_BLOCK + warp;   // grid exact

    // ---- copy precomputed table to shared (straight-line, no branches) ----
    const uint4* gt = reinterpret_cast<const uint4*>(g_tab.w);
    tab[tid] = __ldg(&gt[tid]);                    // tid 0..255
    if (tid < VEC_PER_GRP - THREADS)               // 17 tail entries
        tab[THREADS + tid] = __ldg(&gt[THREADS + tid]);

    // ---- fill per-warp P/Q (pre-scaled inputs) ----
    const float4* xg = reinterpret_cast<const float4*>(x) + (size_t)group * 16;
    if (lane < 16) {
        float4 v = __ldg(&xg[lane]);
        const int row = lane >> 2, part = lane & 3;
        float* P = pq[warp];
        float* Q = pq[warp] + 68;
        const int bi = row * 17 + 1 + part * 4;
        P[bi + 0] = 0.5f * v.x;  P[bi + 1] = 0.5f * v.y;
        P[bi + 2] = 0.5f * v.z;  P[bi + 3] = 0.5f * v.w;
        const float c2 = 0.5f * 0.70710678118654752f;   // 0.5/sqrt(2)
        Q[bi + 0] = c2 * v.x;    Q[bi + 1] = c2 * v.y;
        Q[bi + 2] = c2 * v.z;    Q[bi + 3] = c2 * v.w;
    }
    if (lane < 4) {                          // unit entries for const/linear
        pq[warp][lane * 17]      = 1.0f;
        pq[warp][68 + lane * 17] = 1.0f;
    }
    __syncthreads();

    const unsigned sb = (unsigned)__cvta_generic_to_shared(&pq[warp][0]);
    float4* og = reinterpret_cast<float4*>(out) + (size_t)group * VEC_PER_GRP;

    #pragma unroll
    for (int it = 0; it < 9; ++it) {
        const int k = lane + it * 32;
        if (it < 8 || k < VEC_PER_GRP) {     // 273 = 8*32 + 17
            const uint4 cd = tab[k];
            float4 v;
            v.x = lds_f32(sb + (cd.x & 0xFFFFu)) * lds_f32(sb + (cd.x >> 16));
            v.y = lds_f32(sb + (cd.y & 0xFFFFu)) * lds_f32(sb + (cd.y >> 16));
            v.z = lds_f32(sb + (cd.z & 0xFFFFu)) * lds_f32(sb + (cd.z >> 16));
            v.w = lds_f32(sb + (cd.w & 0xFFFFu)) * lds_f32(sb + (cd.w >> 16));
            stg_cs_v4(og + k, v);            // evict-first streaming store
        }
    }
}

extern "C" void kernel_launch(void* const* d_in, const int* in_sizes, int n_in,
                              void* d_out, int out_size) {
    const float* x = (const float*)d_in[0];
    float* out = (float*)d_out;
    (void)in_sizes; (void)n_in; (void)out_size;

    const int blocks = GROUPS / WARPS_PER_BLOCK;   // 8192
    TaylorExp_14783277432863_kernel<<<blocks, THREADS>>>(x, out);
}